// round 14
// baseline (speedup 1.0000x reference)
#include <cuda_runtime.h>
#include <cstdint>

// Quantum autoencoder forward, batch=256. R14 = R11 (best measured) +
//  - group-phase invariance: per-thread contribution |sum_e e^{i ang_e}|^2 is
//    invariant to a constant angle shift, so terms whose transformed parity
//    vector has rho&7==0 are dropped entirely (C[0] identically 0).
//  - sign table in __constant__ memory (LDC ~30cyc vs LDG ~250-600) to cut the
//    front-end latency chain.
//
// Verified math (R6..R12): X-eigenbasis diagonal simulation; embedding+gates
// are 50 signed terms ang(x) = -1/2 sum_t alpha_t (-1)^{parity(rho_t . x)};
// GF(2) basis transform puts all 7 correlation masks into the low 3 bits of
// x', so with 8 elements/thread the swap-test sum telescopes:
//   P(aux=1) = 0.5 - 2^-14 * sum_threads ( (sum_e re)^2 + (sum_e im)^2 )

#define NUM_Q 10
#define DEPTH 4
#define BATCH 256
#define TPB 128
#define NGATES 40
#define NTERMS 50
#define FULLM 0xFFFFFFFFu

struct XForm {
    unsigned rho[NTERMS];   // transformed parity vectors (10 bits each)
};

__host__ __device__ constexpr int cpar(unsigned v) {
    int n = 0;
    while (v) { n ^= (int)(v & 1u); v >>= 1; }
    return n;
}

__host__ __device__ constexpr unsigned creduce(unsigned v, const unsigned* ech, int ne) {
    for (int i = 0; i < ne; ++i) {
        unsigned h = ech[i];
        unsigned m = 0x200u;
        while (m && !(h & m)) m >>= 1;
        if (v & m) v ^= h;
    }
    return v;
}

__host__ __device__ constexpr XForm make_xform() {
    // circuit Clifford tracking (identical to verified R6 code)
    unsigned lr[NUM_Q] = {}, kc[NUM_Q] = {};
    unsigned rg[NGATES] = {};
    for (int b = 0; b < NUM_Q; ++b) { lr[b] = 1u << b; kc[b] = 1u << b; }
    for (int l = 0; l < DEPTH; ++l) {
        for (int w = 0; w < NUM_Q; ++w) rg[l * NUM_Q + w] = lr[9 - w];
        for (int w = 0; w < NUM_Q; ++w) {
            const int cb = 9 - w;
            const int tb = (w < 9) ? (8 - w) : 9;
            lr[cb] ^= lr[tb];
            kc[tb] ^= kc[cb];
        }
    }
    // invcol = columns of T^{-1}: measurement columns kc0..kc2 first, extend
    unsigned invcol[NUM_Q] = {};
    unsigned ech[NUM_Q] = {};
    int ne = 0;
    for (int c = 0; c < 3; ++c) {
        invcol[c] = kc[c];
        ech[ne++] = creduce(kc[c], ech, ne);
    }
    int cnt = 3;
    for (int b = 0; b < NUM_Q && cnt < NUM_Q; ++b) {
        const unsigned v = 1u << b;
        const unsigned r = creduce(v, ech, ne);
        if (r) { invcol[cnt++] = v; ech[ne++] = r; }
    }
    XForm X{};
    for (int t = 0; t < NTERMS; ++t) {
        const unsigned old = (t < NUM_Q) ? (1u << t) : rg[t - NUM_Q];
        unsigned v = 0;
        for (int j = 0; j < NUM_Q; ++j)
            v |= (unsigned)cpar(old & invcol[j]) << j;
        X.rho[t] = v;
    }
    return X;
}

constexpr XForm TX = make_xform();

// per-tid (7 hi bits of x') sign table: bit t = parity((rho[t]>>3) & tid)
struct PTab { unsigned long long p[128]; };

__host__ __device__ constexpr PTab make_ptab() {
    PTab t{};
    for (unsigned tid = 0; tid < 128; ++tid) {
        unsigned long long v = 0;
        for (int g = 0; g < NTERMS; ++g)
            v |= (unsigned long long)(unsigned)cpar((TX.rho[g] >> 3) & tid) << g;
        t.p[tid] = v;
    }
    return t;
}

__constant__ PTab c_ptab = make_ptab();

// ---- signed terms into group accumulators; m==0 terms dropped (phase inv.) ----
template<int T>
__device__ __forceinline__ void terms(float (&C)[8], const float (&fw)[NUM_Q],
                                      const float (&th)[NGATES],
                                      unsigned plo, unsigned phi) {
    if constexpr (T < NTERMS) {
        constexpr int m = (int)(TX.rho[T] & 7u);
        if constexpr (m != 0) {
            float alpha;
            if constexpr (T < NUM_Q) alpha = fw[9 - T];   // embed term for bit T
            else                     alpha = th[T - NUM_Q];
            unsigned sgn;
            if constexpr (T < 32) sgn = (plo << (31 - T)) & 0x80000000u;
            else                  sgn = (phi << (63 - T)) & 0x80000000u;
            C[m] += __uint_as_float(__float_as_uint(alpha) ^ sgn);
        }
        terms<T + 1>(C, fw, th, plo, phi);
    }
}

__global__ void __launch_bounds__(TPB, 4)
qae_kernel(const float* __restrict__ features,
           const float* __restrict__ weights,
           float* __restrict__ out)
{
    __shared__ float s_wsum[TPB / 32];

    const int tid = threadIdx.x;                   // 0..127, hi 7 bits of x'
    const float* f = features + blockIdx.x * NUM_Q;

    // front-load memory: constant-cache sign mask + the two global loads
    const unsigned long long pm = c_ptab.p[tid];   // LDC, ~30cyc

    float fw[NUM_Q];
#pragma unroll
    for (int q = 0; q < NUM_Q / 2; ++q) {          // row stride 40B -> 8B aligned
        const float2 v = __ldg(reinterpret_cast<const float2*>(f) + q);
        fw[2 * q] = v.x; fw[2 * q + 1] = v.y;
    }
    float th[NGATES];
#pragma unroll
    for (int q = 0; q < NGATES / 4; ++q) {
        const float4 v = __ldg(reinterpret_cast<const float4*>(weights) + q);
        th[4 * q + 0] = v.x; th[4 * q + 1] = v.y;
        th[4 * q + 2] = v.z; th[4 * q + 3] = v.w;
    }

    const unsigned plo = (unsigned)pm;
    const unsigned phi = (unsigned)(pm >> 32);

    // signed terms -> group sums (C[0] stays 0: global per-group phase dropped)
    float C[8] = {0.0f, 0.0f, 0.0f, 0.0f, 0.0f, 0.0f, 0.0f, 0.0f};
    terms<0>(C, fw, th, plo, phi);

    // 3-stage Walsh-Hadamard: ang[e] = -0.5 * sum_m (-1)^{popc(m&e)} C[m]
#pragma unroll
    for (int bit = 1; bit < 8; bit <<= 1) {
#pragma unroll
        for (int i = 0; i < 8; ++i) {
            if (!(i & bit)) {
                const float a = C[i], b = C[i | bit];
                C[i] = a + b;
                C[i | bit] = a - b;
            }
        }
    }

    // 8 unit phasors; telescoped group contribution
    float re[8], im[8];
#pragma unroll
    for (int e = 0; e < 8; ++e)
        __sincosf(-0.5f * C[e], &im[e], &re[e]);

    const float SR = ((re[0] + re[1]) + (re[2] + re[3]))
                   + ((re[4] + re[5]) + (re[6] + re[7]));
    const float SI = ((im[0] + im[1]) + (im[2] + im[3]))
                   + ((im[4] + im[5]) + (im[6] + im[7]));
    float q = fmaf(SR, SR, SI * SI);

    // reduce q over 128 threads
#pragma unroll
    for (int off = 16; off; off >>= 1)
        q += __shfl_xor_sync(FULLM, q, off);
    if ((tid & 31) == 0) s_wsum[tid >> 5] = q;
    __syncthreads();
    if (tid == 0)
        out[blockIdx.x] = 0.5f - ((s_wsum[0] + s_wsum[1]) + (s_wsum[2] + s_wsum[3]))
                                 * 6.103515625e-05f;   // 2^-14
}

extern "C" void kernel_launch(void* const* d_in, const int* in_sizes, int n_in,
                              void* d_out, int out_size)
{
    const float* features = (const float*)d_in[0];  // [256, 10]
    const float* weights  = (const float*)d_in[1];  // [4, 10]
    float* out = (float*)d_out;                     // [256]
    (void)in_sizes; (void)n_in; (void)out_size;

    qae_kernel<<<BATCH, TPB>>>(features, weights, out);
}

// round 15
// speedup vs baseline: 1.0337x; 1.0337x over previous
#include <cuda_runtime.h>
#include <cstdint>

// Quantum autoencoder forward, batch=256. R15 = R11/R14 + MUFU cut.
//
// New insight: kernel is MUFU-throughput bound (2048 MUFU/sample = 524K chip
// ops = ~7.1K cycles at rt=8/SMSP ~= 86% of kernel time; the roofline summary
// hides the XU pipe). Cut: collapse group bit 2 analytically:
//   ang(e0,e1,e2) = P(e0,e1) + (-1)^{e2} Q(e0,e1)
//   sum_{e2} e^{i ang} = 2 e^{iP} cos(Q)
// -> per thread 4 sincos(P) + 4 cos(Q) = 12 MUFU instead of 16.
//   q' = (sum cosP cosQ)^2 + (sum sinP cosQ)^2 ;  P(aux=1) = 0.5 - 2^-12 sum q'
//
// Verified math (R6..R14): X-eigenbasis diagonal simulation; embedding+gates
// are 50 signed terms; GF(2) basis transform puts all 7 correlation masks in
// the low 3 bits of x'; per-8-element-group the swap-test sum telescopes to
// |sum_e e^{i ang_e}|^2; terms with transformed rho&7==0 are a constant group
// phase and are dropped.

#define NUM_Q 10
#define DEPTH 4
#define BATCH 256
#define TPB 128
#define NGATES 40
#define NTERMS 50
#define FULLM 0xFFFFFFFFu

struct XForm {
    unsigned rho[NTERMS];   // transformed parity vectors (10 bits each)
};

__host__ __device__ constexpr int cpar(unsigned v) {
    int n = 0;
    while (v) { n ^= (int)(v & 1u); v >>= 1; }
    return n;
}

__host__ __device__ constexpr unsigned creduce(unsigned v, const unsigned* ech, int ne) {
    for (int i = 0; i < ne; ++i) {
        unsigned h = ech[i];
        unsigned m = 0x200u;
        while (m && !(h & m)) m >>= 1;
        if (v & m) v ^= h;
    }
    return v;
}

__host__ __device__ constexpr XForm make_xform() {
    // circuit Clifford tracking (identical to verified R6 code)
    unsigned lr[NUM_Q] = {}, kc[NUM_Q] = {};
    unsigned rg[NGATES] = {};
    for (int b = 0; b < NUM_Q; ++b) { lr[b] = 1u << b; kc[b] = 1u << b; }
    for (int l = 0; l < DEPTH; ++l) {
        for (int w = 0; w < NUM_Q; ++w) rg[l * NUM_Q + w] = lr[9 - w];
        for (int w = 0; w < NUM_Q; ++w) {
            const int cb = 9 - w;
            const int tb = (w < 9) ? (8 - w) : 9;
            lr[cb] ^= lr[tb];
            kc[tb] ^= kc[cb];
        }
    }
    // invcol = columns of T^{-1}: measurement columns kc0..kc2 first, extend
    unsigned invcol[NUM_Q] = {};
    unsigned ech[NUM_Q] = {};
    int ne = 0;
    for (int c = 0; c < 3; ++c) {
        invcol[c] = kc[c];
        ech[ne++] = creduce(kc[c], ech, ne);
    }
    int cnt = 3;
    for (int b = 0; b < NUM_Q && cnt < NUM_Q; ++b) {
        const unsigned v = 1u << b;
        const unsigned r = creduce(v, ech, ne);
        if (r) { invcol[cnt++] = v; ech[ne++] = r; }
    }
    XForm X{};
    for (int t = 0; t < NTERMS; ++t) {
        const unsigned old = (t < NUM_Q) ? (1u << t) : rg[t - NUM_Q];
        unsigned v = 0;
        for (int j = 0; j < NUM_Q; ++j)
            v |= (unsigned)cpar(old & invcol[j]) << j;
        X.rho[t] = v;
    }
    return X;
}

constexpr XForm TX = make_xform();

// per-tid (7 hi bits of x') sign table: bit t = parity((rho[t]>>3) & tid)
struct PTab { unsigned long long p[128]; };

__host__ __device__ constexpr PTab make_ptab() {
    PTab t{};
    for (unsigned tid = 0; tid < 128; ++tid) {
        unsigned long long v = 0;
        for (int g = 0; g < NTERMS; ++g)
            v |= (unsigned long long)(unsigned)cpar((TX.rho[g] >> 3) & tid) << g;
        t.p[tid] = v;
    }
    return t;
}

__constant__ PTab c_ptab = make_ptab();

// ---- signed terms: masks m=1..3 -> CP[m], m=4..7 -> CQ[m-4]; m==0 dropped ----
template<int T>
__device__ __forceinline__ void terms(float (&CP)[4], float (&CQ)[4],
                                      const float (&fw)[NUM_Q],
                                      const float (&th)[NGATES],
                                      unsigned plo, unsigned phi) {
    if constexpr (T < NTERMS) {
        constexpr int m = (int)(TX.rho[T] & 7u);
        if constexpr (m != 0) {
            float alpha;
            if constexpr (T < NUM_Q) alpha = fw[9 - T];   // embed term for bit T
            else                     alpha = th[T - NUM_Q];
            unsigned sgn;
            if constexpr (T < 32) sgn = (plo << (31 - T)) & 0x80000000u;
            else                  sgn = (phi << (63 - T)) & 0x80000000u;
            const float sv = __uint_as_float(__float_as_uint(alpha) ^ sgn);
            if constexpr (m < 4) CP[m] += sv;
            else                 CQ[m - 4] += sv;
        }
        terms<T + 1>(CP, CQ, fw, th, plo, phi);
    }
}

__global__ void __launch_bounds__(TPB, 4)
qae_kernel(const float* __restrict__ features,
           const float* __restrict__ weights,
           float* __restrict__ out)
{
    __shared__ float s_wsum[TPB / 32];

    const int tid = threadIdx.x;                   // 0..127, hi 7 bits of x'
    const float* f = features + blockIdx.x * NUM_Q;

    // front-load memory: constant-cache sign mask + the two global loads
    const unsigned long long pm = c_ptab.p[tid];

    float fw[NUM_Q];
#pragma unroll
    for (int q = 0; q < NUM_Q / 2; ++q) {          // row stride 40B -> 8B aligned
        const float2 v = __ldg(reinterpret_cast<const float2*>(f) + q);
        fw[2 * q] = v.x; fw[2 * q + 1] = v.y;
    }
    float th[NGATES];
#pragma unroll
    for (int q = 0; q < NGATES / 4; ++q) {
        const float4 v = __ldg(reinterpret_cast<const float4*>(weights) + q);
        th[4 * q + 0] = v.x; th[4 * q + 1] = v.y;
        th[4 * q + 2] = v.z; th[4 * q + 3] = v.w;
    }

    const unsigned plo = (unsigned)pm;
    const unsigned phi = (unsigned)(pm >> 32);

    // signed terms -> P-part (bit2 clear) and Q-part (bit2 set) accumulators
    float CP[4] = {0.0f, 0.0f, 0.0f, 0.0f};   // CP[0] stays 0 (phase dropped)
    float CQ[4] = {0.0f, 0.0f, 0.0f, 0.0f};
    terms<0>(CP, CQ, fw, th, plo, phi);

    // two 2-bit Walsh-Hadamards: P[e'], Q[e'] for e' in 0..3
#pragma unroll
    for (int bit = 1; bit < 4; bit <<= 1) {
#pragma unroll
        for (int i = 0; i < 4; ++i) {
            if (!(i & bit)) {
                float a = CP[i], b = CP[i | bit];
                CP[i] = a + b; CP[i | bit] = a - b;
                a = CQ[i]; b = CQ[i | bit];
                CQ[i] = a + b; CQ[i | bit] = a - b;
            }
        }
    }

    // group sum with bit-2 collapsed: sum_e e^{i ang} = 2 sum_{e'} e^{iP'}cos(Q')
    // (factor 2 folded into the final 2^-12 scale)
    float SR = 0.0f, SI = 0.0f;
#pragma unroll
    for (int e = 0; e < 4; ++e) {
        float sp, cp;
        __sincosf(-0.5f * CP[e], &sp, &cp);
        const float cq = __cosf(0.5f * CQ[e]);     // cos is even
        SR = fmaf(cp, cq, SR);
        SI = fmaf(sp, cq, SI);
    }
    float q = fmaf(SR, SR, SI * SI);

    // reduce q over 128 threads
#pragma unroll
    for (int off = 16; off; off >>= 1)
        q += __shfl_xor_sync(FULLM, q, off);
    if ((tid & 31) == 0) s_wsum[tid >> 5] = q;
    __syncthreads();
    if (tid == 0)
        out[blockIdx.x] = 0.5f - ((s_wsum[0] + s_wsum[1]) + (s_wsum[2] + s_wsum[3]))
                                 * 2.44140625e-04f;   // 2^-12 (includes the 2^2)
}

extern "C" void kernel_launch(void* const* d_in, const int* in_sizes, int n_in,
                              void* d_out, int out_size)
{
    const float* features = (const float*)d_in[0];  // [256, 10]
    const float* weights  = (const float*)d_in[1];  // [4, 10]
    float* out = (float*)d_out;                     // [256]
    (void)in_sizes; (void)n_in; (void)out_size;

    qae_kernel<<<BATCH, TPB>>>(features, weights, out);
}